// round 14
// baseline (speedup 1.0000x reference)
#include <cuda_runtime.h>
#include <cstdint>

// Problem constants (fixed by the reference)
#define BB 2
#define LL 1024
#define MM 8
#define NN 16
#define CC 16
#define HH 64
#define WW 64
#define VOTES (MM * NN)            // 128
#define SLAB  (CC * HH * WW)       // 65536 floats = 256 KB per (b,l)
#define CGRP  4                    // channels per quantum
#define NGRP  (CC / CGRP)          // 4 quanta per slab
#define PLANE (HH * WW)            // 4096
#define QFLOATS (CGRP * PLANE)     // 16384 floats = 64 KB per quantum
#define TPB   512                  // block size (CGRP * VOTES)

// Final design-space cell: 64 KB quantum at CONSTANT per-thread cost
// (vs R13: same 8 STG.128 + 1 atomic per thread; half the barriers/prologues
// per slab; wider 512-thread barrier; 4x gather duplication — all cheap).
// ALL 512 threads gather vote (t & 127); thread commits channel (t >> 7):
//   gather -> stream-zero 64 KB -> __syncthreads -> ONE atomicAdd each.
__global__ __launch_bounds__(TPB, 4)
void ht_vote_kernel(const float* __restrict__ feats,   // [B,L,N,C]
                    const int*   __restrict__ vsrc,    // [B,L,2]
                    const int*   __restrict__ vdst,    // [B,L,2]
                    const int*   __restrict__ isrc,    // [B,L,M]
                    const int*   __restrict__ idst,    // [B,L,N]
                    float* __restrict__ out)           // [B,L,C,H,W]
{
    const int q  = blockIdx.x;         // 0 .. B*L*NGRP-1
    const int bl = q >> 2;             // NGRP == 4
    const int g  = q & 3;              // channel group
    const int b  = bl >> 10;           // LL == 1024
    const int t  = threadIdx.x;
    const int v  = t & 127;            // vote id (each vote handled 4x)
    const int c  = t >> 7;             // channel within group (0..3)

    // ---- Gather chain (all threads): issued before the store stream; the
    // ~3 dependent L2 latencies hide under the 64 KB of independent stores.
    const int m = v >> 4;              // NN == 16
    const int n = v & 15;

    const int s  = isrc[bl * MM + m];
    const int d  = idst[(b * LL + s) * NN + n];
    const int sy = vsrc[(b * LL + s) * 2 + 0];
    const int sx = vsrc[(b * LL + s) * 2 + 1];
    const int dy = vdst[(b * LL + d) * 2 + 0];
    const int dx = vdst[(b * LL + d) * 2 + 1];

    // voxels are int32: floor(float sub) == integer sub exactly
    const int by = dy - sy + HH / 2;
    const int bx = dx - sx + WW / 2;
    int bin = -1;
    if (((unsigned)by < HH) & ((unsigned)bx < WW)) bin = by * WW + bx;

    // this thread's single channel weight (scalar LDG, L2-hot)
    const float w = feats[(((size_t)(b * LL + s)) * NN + n) * CC + g * CGRP + c];

    float* base = out + (size_t)bl * SLAB + g * QFLOATS;

    // ---- Stream-zero this quantum's 64 KB (8 float4 per thread) ----
    {
        float4* b4 = (float4*)base;
        const float4 z = make_float4(0.f, 0.f, 0.f, 0.f);
#pragma unroll
        for (int i = 0; i < QFLOATS / 4 / TPB; i++)
            b4[t + i * TPB] = z;
    }

    __syncthreads();   // all zero-stores of this CTA-private quantum complete
                       // & visible before any scattered atomic touches it

    // ---- Scatter: exactly one atomicAdd per thread (REDG, L2-hot) ----
    if (bin >= 0)
        atomicAdd(base + c * PLANE + bin, w);
}

extern "C" void kernel_launch(void* const* d_in, const int* in_sizes, int n_in,
                              void* d_out, int out_size)
{
    const float* feats = (const float*)d_in[0];   // [B,L,N,C] f32
    const int*   vsrc  = (const int*)  d_in[1];   // [B,L,2]   i32
    const int*   vdst  = (const int*)  d_in[2];   // [B,L,2]   i32
    const int*   isrc  = (const int*)  d_in[3];   // [B,L,M]   i32
    const int*   idst  = (const int*)  d_in[4];   // [B,L,N]   i32
    float*       out   = (float*)d_out;           // [B,L,C,H,W] f32

    ht_vote_kernel<<<BB * LL * NGRP, TPB>>>(feats, vsrc, vdst, isrc, idst, out);
}

// round 15
// speedup vs baseline: 1.0024x; 1.0024x over previous
#include <cuda_runtime.h>
#include <cstdint>

// Problem constants (fixed by the reference)
#define BB 2
#define LL 1024
#define MM 8
#define NN 16
#define CC 16
#define HH 64
#define WW 64
#define VOTES (MM * NN)            // 128
#define SLAB  (CC * HH * WW)       // 65536 floats = 256 KB per (b,l)
#define CGRP  2                    // channels per quantum (measured optimum)
#define PLANE (HH * WW)            // 4096
#define QFLOATS (CGRP * PLANE)     // 8192 floats = 32 KB per quantum
#define NPAIR 4                    // quantum-pairs per slab (16 ch / 4 per pair)

// R13 champion, software-pipelined over a PAIR of 32 KB quanta per CTA:
//   zero Q1 -> sync -> { atomics Q1 || zero Q2 } -> sync -> atomics Q2
// Q1's atomic tail (fire-and-forget REDG, disjoint from Q2's region) is
// deterministically hidden under the CTA's own Q2 store stream; only Q2's
// tail remains exposed -> exposed tail time per slab halves vs R13.
// Per-thread per-quantum cost identical to R13: 8 STG.128 + 1 atomic + 1 sync.
__global__ __launch_bounds__(256, 8)
void ht_vote_kernel(const float* __restrict__ feats,   // [B,L,N,C]
                    const int*   __restrict__ vsrc,    // [B,L,2]
                    const int*   __restrict__ vdst,    // [B,L,2]
                    const int*   __restrict__ isrc,    // [B,L,M]
                    const int*   __restrict__ idst,    // [B,L,N]
                    float* __restrict__ out)           // [B,L,C,H,W]
{
    const int q  = blockIdx.x;         // 0 .. B*L*NPAIR-1
    const int bl = q >> 2;             // NPAIR == 4
    const int gp = q & 3;              // quantum-pair: channels [4gp, 4gp+4)
    const int b  = bl >> 10;           // LL == 1024
    const int t  = threadIdx.x;
    const int v  = t & 127;            // vote id (each vote handled twice)
    const int c  = t >> 7;             // channel within quantum (0 or 1)

    // ---- Gather chain (all threads, once for both quanta): issued before
    // the store streams; dependent L2 latencies hide under them.
    const int m = v >> 4;              // NN == 16
    const int n = v & 15;

    const int s  = isrc[bl * MM + m];
    const int d  = idst[(b * LL + s) * NN + n];
    const int sy = vsrc[(b * LL + s) * 2 + 0];
    const int sx = vsrc[(b * LL + s) * 2 + 1];
    const int dy = vdst[(b * LL + d) * 2 + 0];
    const int dx = vdst[(b * LL + d) * 2 + 1];

    // voxels are int32: floor(float sub) == integer sub exactly
    const int by = dy - sy + HH / 2;
    const int bx = dx - sx + WW / 2;
    int bin = -1;
    if (((unsigned)by < HH) & ((unsigned)bx < WW)) bin = by * WW + bx;

    // this thread's channel weight in each quantum of the pair (L2-hot)
    const float* frow = feats + (((size_t)(b * LL + s)) * NN + n) * CC + 4 * gp;
    const float w1 = frow[c];          // quantum 1: channel 4gp + c
    const float w2 = frow[2 + c];      // quantum 2: channel 4gp + 2 + c

    float* base1 = out + (size_t)bl * SLAB + (size_t)gp * 2 * QFLOATS;
    float* base2 = base1 + QFLOATS;
    const float4 z = make_float4(0.f, 0.f, 0.f, 0.f);

    // ---- Zero Q1 (32 KB, 8 float4 per thread) ----
    {
        float4* b4 = (float4*)base1;
#pragma unroll
        for (int i = 0; i < QFLOATS / 4 / 256; i++)
            b4[t + i * 256] = z;
    }
    __syncthreads();   // Q1 zeroes complete before Q1 atomics

    // ---- Atomics Q1 (fire-and-forget) overlapped with zero Q2 ----
    if (bin >= 0)
        atomicAdd(base1 + c * PLANE + bin, w1);
    {
        float4* b4 = (float4*)base2;
#pragma unroll
        for (int i = 0; i < QFLOATS / 4 / 256; i++)
            b4[t + i * 256] = z;
    }
    __syncthreads();   // Q2 zeroes complete before Q2 atomics

    // ---- Atomics Q2 (only exposed tail of the pair) ----
    if (bin >= 0)
        atomicAdd(base2 + c * PLANE + bin, w2);
}

extern "C" void kernel_launch(void* const* d_in, const int* in_sizes, int n_in,
                              void* d_out, int out_size)
{
    const float* feats = (const float*)d_in[0];   // [B,L,N,C] f32
    const int*   vsrc  = (const int*)  d_in[1];   // [B,L,2]   i32
    const int*   vdst  = (const int*)  d_in[2];   // [B,L,2]   i32
    const int*   isrc  = (const int*)  d_in[3];   // [B,L,M]   i32
    const int*   idst  = (const int*)  d_in[4];   // [B,L,N]   i32
    float*       out   = (float*)d_out;           // [B,L,C,H,W] f32

    ht_vote_kernel<<<BB * LL * NPAIR, 256>>>(feats, vsrc, vdst, isrc, idst, out);
}